// round 5
// baseline (speedup 1.0000x reference)
#include <cuda_runtime.h>

// Demolition_Conv2d: grouped conv (16 groups of 1->32, 3x3, pad 1) + bias,
// per-(cin,cout) 5-bit quant-dequant (scale=15/9), sum over cin.
//
// R5: kill pair-construction ALU. Prepass materializes two zero-padded pair
// streams in device scratch:
//   E[b,c,hp,i] = (x[2i],   x[2i+1])   (even-aligned pairs)
//   O[b,c,hp,i] = (x[2i-1], x[2i])     (odd-aligned pairs)
// Main kernel: 8 pixels x 4 couts per thread; all 9 taps/row are direct
// vector loads from E/O (no pk2, no boundary selects). FFMA2 everywhere.

#define CIN  16
#define COUT 32
#define HH   112
#define WW   112
#define NB   8     // batch
#define NC   4     // couts per thread
#define HP   114   // padded rows (one zero row above/below)
#define PW   58    // pairs per padded row

typedef unsigned long long f2;

__device__ __align__(16) f2 g_E[NB * CIN * HP * PW];   // ~6.8 MB
__device__ __align__(16) f2 g_O[NB * CIN * HP * PW];   // ~6.8 MB

__device__ __forceinline__ f2 pk2(float lo, float hi) {
    f2 r; asm("mov.b64 %0, {%1, %2};" : "=l"(r) : "f"(lo), "f"(hi)); return r;
}
__device__ __forceinline__ void fma2i(f2& acc, f2 a, f2 b) {
    asm("fma.rn.f32x2 %0, %1, %2, %0;" : "+l"(acc) : "l"(a), "l"(b));
}
__device__ __forceinline__ void add2i(f2& acc, f2 b) {
    asm("add.rn.f32x2 %0, %0, %1;" : "+l"(acc) : "l"(b));
}
__device__ __forceinline__ f2 mul2(f2 a, f2 b) {
    f2 d; asm("mul.rn.f32x2 %0, %1, %2;" : "=l"(d) : "l"(a), "l"(b)); return d;
}

// ---------------- prepass: build E/O pair streams ----------------
__global__ __launch_bounds__(256)
void prepass_kernel(const float* __restrict__ x)
{
    int gid = blockIdx.x * 256 + threadIdx.x;        // [0, NB*CIN*HP*PW)
    int i  = gid % PW;
    int t  = gid / PW;
    int hp = t % HP;
    int bc = t / HP;
    int hrow = hp - 1;
    bool rv = (hrow >= 0) && (hrow < HH);
    const float* row = x + (bc * HH + hrow) * WW;
    int w0 = 2 * i;
    float xm1 = (rv && w0 >= 1 && w0 - 1 < WW) ? row[w0 - 1] : 0.0f;
    float x0  = (rv && w0 < WW)                ? row[w0]     : 0.0f;
    float x1  = (rv && w0 + 1 < WW)            ? row[w0 + 1] : 0.0f;
    g_E[gid] = pk2(x0, x1);
    g_O[gid] = pk2(xm1, x0);
}

// ---------------- main kernel ----------------
__global__ __launch_bounds__(128)
void demolition_conv2d_kernel(const float* __restrict__ Wt,
                              const float* __restrict__ bias,
                              float* __restrict__ out)
{
    // This block's 4 couts: [w0..w8, bias]*SCALE per (cin, lc), dup pairs.
    __shared__ __align__(16) f2 sW[CIN * NC * 10];   // 5 KB

    const float SCALEf = 15.0f / 9.0f;
    const float INVf   = 9.0f / 15.0f;
    const float MAGICf = 12582912.0f;   // 1.5 * 2^23

    // g in [0, 100352). 12544 8-pixel tiles; cout group uniform per block.
    int g = blockIdx.x * 128 + threadIdx.x;
    int grp = g / 12544;                // 0..7
    int t  = g % 12544;
    int tw = t % 14;                    // 112/8 tiles per row
    int t1 = t / 14;
    int h  = t1 % HH;
    int b  = t1 / HH;
    int wp = tw * 4;                    // first pair index (w0 = 8*tw)
    int co_base = grp * NC;

    for (int i = threadIdx.x; i < CIN * NC * 10; i += 128) {
        int e   = i / 10;
        int k   = i % 10;
        int cin = e / NC;
        int lc  = e % NC;
        int co  = co_base + lc;
        float v = (k < 9) ? Wt[(cin * COUT + co) * 9 + k] : bias[cin * COUT + co];
        v *= SCALEf;
        sW[i] = pk2(v, v);
    }
    __syncthreads();

    const f2 MAG2  = pk2(MAGICf,  MAGICf);
    const f2 NMAG2 = pk2(-MAGICf, -MAGICf);
    const f2 INV2  = pk2(INVf,    INVf);

    f2 acc[NC][4];
#pragma unroll
    for (int c = 0; c < NC; ++c)
#pragma unroll
        for (int j = 0; j < 4; ++j) acc[c][j] = 0ULL;

#pragma unroll 1
    for (int cin = 0; cin < CIN; ++cin) {
        // Padded row block starts at hp = h (covers x rows h-1, h, h+1).
        long base = ((long)(b * CIN + cin) * HP + h) * PW + wp;
        const f2* Ep = g_E + base;
        const f2* Op = g_O + base;

        f2 e[3][4], o[3][5];
#pragma unroll
        for (int r = 0; r < 3; ++r) {
            const ulonglong2* e2 = reinterpret_cast<const ulonglong2*>(Ep + r * PW);
            const ulonglong2* o2 = reinterpret_cast<const ulonglong2*>(Op + r * PW);
            ulonglong2 ea = e2[0], eb = e2[1];
            ulonglong2 oa = o2[0], ob = o2[1];
            e[r][0] = ea.x; e[r][1] = ea.y; e[r][2] = eb.x; e[r][3] = eb.y;
            o[r][0] = oa.x; o[r][1] = oa.y; o[r][2] = ob.x; o[r][3] = ob.y;
            o[r][4] = Op[r * PW + 4];
        }

        const ulonglong2* wbase =
            reinterpret_cast<const ulonglong2*>(&sW[cin * NC * 10]);

#pragma unroll
        for (int c = 0; c < NC; ++c) {
            ulonglong2 w01 = wbase[c * 5 + 0];
            ulonglong2 w23 = wbase[c * 5 + 1];
            ulonglong2 w45 = wbase[c * 5 + 2];
            ulonglong2 w67 = wbase[c * 5 + 3];
            ulonglong2 w8b = wbase[c * 5 + 4];   // .x = w8, .y = bias

            f2 y[4];
#pragma unroll
            for (int j = 0; j < 4; ++j) y[j] = w8b.y;

#pragma unroll
            for (int j = 0; j < 4; ++j) {
                fma2i(y[j], o[0][j],     w01.x);
                fma2i(y[j], e[0][j],     w01.y);
                fma2i(y[j], o[0][j + 1], w23.x);
                fma2i(y[j], o[1][j],     w23.y);
                fma2i(y[j], e[1][j],     w45.x);
                fma2i(y[j], o[1][j + 1], w45.y);
                fma2i(y[j], o[2][j],     w67.x);
                fma2i(y[j], e[2][j],     w67.y);
                fma2i(y[j], o[2][j + 1], w8b.x);
            }

#pragma unroll
            for (int j = 0; j < 4; ++j) {
                add2i(y[j], MAG2);        // RNE to integer (magic)
                add2i(y[j], NMAG2);
                add2i(acc[c][j], y[j]);   // exact integer-valued sum
            }
        }
    }

    float* ob = out + ((b * COUT + co_base) * HH + h) * WW + tw * 8;
#pragma unroll
    for (int c = 0; c < NC; ++c) {
        ulonglong2 lo, hi;
        lo.x = mul2(acc[c][0], INV2);
        lo.y = mul2(acc[c][1], INV2);
        hi.x = mul2(acc[c][2], INV2);
        hi.y = mul2(acc[c][3], INV2);
        *reinterpret_cast<ulonglong2*>(ob + c * HH * WW)     = lo;
        *reinterpret_cast<ulonglong2*>(ob + c * HH * WW + 4) = hi;
    }
}

extern "C" void kernel_launch(void* const* d_in, const int* in_sizes, int n_in,
                              void* d_out, int out_size)
{
    const float* x    = (const float*)d_in[0];   // [8,16,112,112]
    const float* Wt   = (const float*)d_in[1];   // [16,32,1,3,3]
    const float* bias = (const float*)d_in[2];   // [16,32]
    float* out        = (float*)d_out;           // [8,32,112,112]

    // NB*CIN*HP*PW = 846336 = 3306 * 256 exactly.
    prepass_kernel<<<3306, 256>>>(x);
    demolition_conv2d_kernel<<<784, 128>>>(Wt, bias, out);
}